// round 1
// baseline (speedup 1.0000x reference)
#include <cuda_runtime.h>
#include <cuda_bf16.h>
#include <math.h>

// ---------------- problem constants ----------------
#define NMAX   50048          // nodes (50000, padded)
#define DH     256            // hidden dim
#define COUT   10             // output classes
#define EMAX   860064         // edges incl. self loops (800000 + 50000, padded)

// ---------------- device scratch (no allocations allowed) ----------------
__device__ float g_h [ (size_t)NMAX * DH ];   // GEMM output / gather source
__device__ float g_y [ (size_t)NMAX * DH ];   // aggregation target / next input
__device__ float g_h3[ (size_t)NMAX * COUT ];
__device__ float g_as[NMAX];
__device__ float g_ad[NMAX];
__device__ float g_m [NMAX];
__device__ float g_den[NMAX];
__device__ float g_e [EMAX];
__device__ float g_p [EMAX];
__device__ int   g_is64;

// ---------------- helpers ----------------
__device__ __forceinline__ void atomicMaxFloat(float* addr, float val) {
    if (val >= 0.0f) atomicMax((int*)addr, __float_as_int(val));
    else             atomicMin((unsigned int*)addr, (unsigned int)__float_as_int(val));
}

__device__ __forceinline__ void redAdd4(float* p, float4 v) {
    asm volatile("red.global.add.v4.f32 [%0], {%1,%2,%3,%4};"
                 :: "l"(p), "f"(v.x), "f"(v.y), "f"(v.z), "f"(v.w) : "memory");
}

__device__ __forceinline__ void get_edge(const void* ei, int E, int N, int i,
                                         int& s, int& d) {
    if (i < E) {
        if (g_is64) {
            const long long* p = (const long long*)ei;
            s = (int)p[i]; d = (int)p[E + i];
        } else {
            const int* p = (const int*)ei;
            s = p[i]; d = p[E + i];
        }
    } else {
        s = i - E; d = s;   // self loop
    }
}

// Detect whether edge_index is int64 or int32. If int64 (values < 2^31),
// every odd 32-bit word is 0. If int32, odd words are random node ids.
__global__ void detect_width_kernel(const int* ei2, int E) {
    __shared__ int any;
    if (threadIdx.x == 0) any = 0;
    __syncthreads();
    int limit = min(E, 2048);
    for (int j = threadIdx.x; j < limit; j += blockDim.x)
        if (ei2[2 * j + 1] != 0) any = 1;
    __syncthreads();
    if (threadIdx.x == 0) g_is64 = (any ? 0 : 1);
}

// ---------------- SGEMM: C[M,256] = act(A[M,256]) @ B[256,256] ----------------
// classic 128x128x8 register-tiled fp32 kernel, 256 threads, 8x8 microtile
template<bool RELU>
__global__ void __launch_bounds__(256, 2)
sgemm128(const float* __restrict__ A, const float* __restrict__ B,
         float* __restrict__ C, int M) {
    const int K = 256, N = 256;
    __shared__ float As[8][128];
    __shared__ float Bs[8][128];

    int tid = threadIdx.x;
    int bm = blockIdx.y, bn = blockIdx.x;

    int rowA = tid >> 1;            // 0..127
    int colA = (tid & 1) * 4;       // 0 or 4
    int rowB = tid >> 5;            // 0..7
    int colB = (tid & 31) * 4;      // 0..124
    int tx = tid & 15, ty = tid >> 4;

    float acc[8][8];
#pragma unroll
    for (int i = 0; i < 8; i++)
#pragma unroll
        for (int j = 0; j < 8; j++) acc[i][j] = 0.0f;

    int gRowA = bm * 128 + rowA;
    bool aValid = gRowA < M;
    const float* Aptr = A + (size_t)gRowA * K + colA;
    const float* Bptr = B + (size_t)rowB * N + bn * 128 + colB;

    for (int k0 = 0; k0 < K; k0 += 8) {
        float4 av = aValid ? *(const float4*)(Aptr + k0) : make_float4(0, 0, 0, 0);
        if (RELU) {
            av.x = fmaxf(av.x, 0.0f); av.y = fmaxf(av.y, 0.0f);
            av.z = fmaxf(av.z, 0.0f); av.w = fmaxf(av.w, 0.0f);
        }
        As[colA + 0][rowA] = av.x;
        As[colA + 1][rowA] = av.y;
        As[colA + 2][rowA] = av.z;
        As[colA + 3][rowA] = av.w;

        *(float4*)&Bs[rowB][colB] = *(const float4*)(Bptr + (size_t)k0 * N);
        __syncthreads();

#pragma unroll
        for (int k = 0; k < 8; k++) {
            float a[8], b[8];
            *(float4*)&a[0] = *(const float4*)&As[k][ty * 8];
            *(float4*)&a[4] = *(const float4*)&As[k][ty * 8 + 4];
            *(float4*)&b[0] = *(const float4*)&Bs[k][tx * 8];
            *(float4*)&b[4] = *(const float4*)&Bs[k][tx * 8 + 4];
#pragma unroll
            for (int i = 0; i < 8; i++)
#pragma unroll
                for (int j = 0; j < 8; j++)
                    acc[i][j] = fmaf(a[i], b[j], acc[i][j]);
        }
        __syncthreads();
    }

#pragma unroll
    for (int i = 0; i < 8; i++) {
        int r = bm * 128 + ty * 8 + i;
        if (r < M) {
            float* cp = C + (size_t)r * N + bn * 128 + tx * 8;
            float4 v0 = make_float4(acc[i][0], acc[i][1], acc[i][2], acc[i][3]);
            float4 v1 = make_float4(acc[i][4], acc[i][5], acc[i][6], acc[i][7]);
            *(float4*)cp = v0;
            *(float4*)(cp + 4) = v1;
        }
    }
}

// ---------------- per-node prep: alphas + init m/den + y-row = bias ----------------
__global__ void node_prep(const float* __restrict__ h,
                          const float* __restrict__ a_src,
                          const float* __restrict__ a_dst,
                          const float* __restrict__ b,
                          float* __restrict__ y, int N) {
    int n = (blockIdx.x * blockDim.x + threadIdx.x) >> 5;
    int lane = threadIdx.x & 31;
    if (n >= N) return;
    const float4* hr = (const float4*)(h + (size_t)n * DH);
    float4* yr = (float4*)(y + (size_t)n * DH);
    const float4* as4 = (const float4*)a_src;
    const float4* ad4 = (const float4*)a_dst;
    const float4* b4 = (const float4*)b;
    float ss = 0.0f, sd = 0.0f;
#pragma unroll
    for (int i = lane; i < DH / 4; i += 32) {
        float4 v = hr[i];
        float4 sa = as4[i];
        float4 da = ad4[i];
        ss += v.x * sa.x + v.y * sa.y + v.z * sa.z + v.w * sa.w;
        sd += v.x * da.x + v.y * da.y + v.z * da.z + v.w * da.w;
        yr[i] = b4[i];
    }
#pragma unroll
    for (int o = 16; o > 0; o >>= 1) {
        ss += __shfl_xor_sync(0xFFFFFFFFu, ss, o);
        sd += __shfl_xor_sync(0xFFFFFFFFu, sd, o);
    }
    if (lane == 0) {
        g_as[n] = ss;
        g_ad[n] = sd;
        g_m[n] = -INFINITY;
        g_den[n] = 0.0f;
    }
}

// ---------------- edge passes ----------------
__global__ void edge_max(const void* __restrict__ ei, int E, int N) {
    int i = blockIdx.x * blockDim.x + threadIdx.x;
    if (i >= E + N) return;
    int s, d;
    get_edge(ei, E, N, i, s, d);
    float v = g_as[s] + g_ad[d];
    v = v > 0.0f ? v : 0.2f * v;       // leaky_relu(0.2)
    g_e[i] = v;
    atomicMaxFloat(&g_m[d], v);
}

__global__ void edge_sum(const void* __restrict__ ei, int E, int N) {
    int i = blockIdx.x * blockDim.x + threadIdx.x;
    if (i >= E + N) return;
    int s, d;
    get_edge(ei, E, N, i, s, d);
    float p = __expf(g_e[i] - g_m[d]);
    g_p[i] = p;
    atomicAdd(&g_den[d], p);
}

__global__ void edge_agg256(const void* __restrict__ ei, int E, int N,
                            const float* __restrict__ h, float* __restrict__ y) {
    int gt = blockIdx.x * blockDim.x + threadIdx.x;
    int e = gt >> 5;
    int lane = gt & 31;
    if (e >= E + N) return;
    int s, d;
    get_edge(ei, E, N, e, s, d);
    float coeff = g_p[e] / g_den[d];
    const float4* hs = (const float4*)(h + (size_t)s * DH);
    float* yd = y + (size_t)d * DH;
#pragma unroll
    for (int i = lane; i < DH / 4; i += 32) {
        float4 v = hs[i];
        v.x *= coeff; v.y *= coeff; v.z *= coeff; v.w *= coeff;
        redAdd4(yd + i * 4, v);
    }
}

__global__ void edge_agg10(const void* __restrict__ ei, int E, int N,
                           const float* __restrict__ h3, float* __restrict__ out) {
    int e = blockIdx.x * blockDim.x + threadIdx.x;
    if (e >= E + N) return;
    int s, d;
    get_edge(ei, E, N, e, s, d);
    float coeff = g_p[e] / g_den[d];
    const float* hs = h3 + (size_t)s * COUT;
    float* od = out + (size_t)d * COUT;
#pragma unroll
    for (int c = 0; c < COUT; c++)
        atomicAdd(&od[c], coeff * hs[c]);
}

// ---------------- layer 3 GEMM (D_out = 10), warp per node ----------------
__global__ void gemm_node3(const float* __restrict__ in, const float* __restrict__ W,
                           const float* __restrict__ a_s, const float* __restrict__ a_d,
                           const float* __restrict__ b, float* __restrict__ h3,
                           float* __restrict__ out, int N) {
    int n = (blockIdx.x * blockDim.x + threadIdx.x) >> 5;
    int lane = threadIdx.x & 31;
    if (n >= N) return;
    float acc[COUT];
#pragma unroll
    for (int c = 0; c < COUT; c++) acc[c] = 0.0f;
    const float* xr = in + (size_t)n * DH;
#pragma unroll
    for (int i = 0; i < DH / 32; i++) {
        int k = lane + i * 32;
        float v = fmaxf(xr[k], 0.0f);                 // relu on input
#pragma unroll
        for (int c = 0; c < COUT; c++)
            acc[c] = fmaf(v, W[k * COUT + c], acc[c]);
    }
#pragma unroll
    for (int c = 0; c < COUT; c++)
#pragma unroll
        for (int o = 16; o > 0; o >>= 1)
            acc[c] += __shfl_xor_sync(0xFFFFFFFFu, acc[c], o);
    if (lane == 0) {
        float ss = 0.0f, sd = 0.0f;
#pragma unroll
        for (int c = 0; c < COUT; c++) {
            h3[(size_t)n * COUT + c] = acc[c];
            out[(size_t)n * COUT + c] = b[c];         // init output row with bias
            ss = fmaf(acc[c], a_s[c], ss);
            sd = fmaf(acc[c], a_d[c], sd);
        }
        g_as[n] = ss;
        g_ad[n] = sd;
        g_m[n] = -INFINITY;
        g_den[n] = 0.0f;
    }
}

// ---------------- host launcher ----------------
extern "C" void kernel_launch(void* const* d_in, const int* in_sizes, int n_in,
                              void* d_out, int out_size) {
    const float* x      = (const float*)d_in[0];
    const void*  ei     = d_in[1];
    const float* W1     = (const float*)d_in[2];
    const float* a_src1 = (const float*)d_in[3];
    const float* a_dst1 = (const float*)d_in[4];
    const float* b1     = (const float*)d_in[5];
    const float* W2     = (const float*)d_in[6];
    const float* a_src2 = (const float*)d_in[7];
    const float* a_dst2 = (const float*)d_in[8];
    const float* b2     = (const float*)d_in[9];
    const float* W3     = (const float*)d_in[10];
    const float* a_src3 = (const float*)d_in[11];
    const float* a_dst3 = (const float*)d_in[12];
    const float* b3     = (const float*)d_in[13];

    int N = in_sizes[0] / DH;      // 50000
    int E = in_sizes[1] / 2;       // 800000
    int ET = E + N;                // with self-loops

    float *h, *y, *h3;
    cudaGetSymbolAddress((void**)&h,  g_h);
    cudaGetSymbolAddress((void**)&y,  g_y);
    cudaGetSymbolAddress((void**)&h3, g_h3);
    float* out = (float*)d_out;

    detect_width_kernel<<<1, 256>>>((const int*)ei, E);

    dim3 ggrid(2, (N + 127) / 128);
    int nodeBlocks = (N * 32 + 255) / 256;
    int edgeBlocks = (ET + 255) / 256;
    int aggBlocks  = ((size_t)ET * 32 + 255) / 256;

    // ---- layer 1 ----
    sgemm128<false><<<ggrid, 256>>>(x, W1, h, N);
    node_prep<<<nodeBlocks, 256>>>(h, a_src1, a_dst1, b1, y, N);
    edge_max<<<edgeBlocks, 256>>>(ei, E, N);
    edge_sum<<<edgeBlocks, 256>>>(ei, E, N);
    edge_agg256<<<aggBlocks, 256>>>(ei, E, N, h, y);

    // ---- layer 2 ----
    sgemm128<true><<<ggrid, 256>>>(y, W2, h, N);
    node_prep<<<nodeBlocks, 256>>>(h, a_src2, a_dst2, b2, y, N);
    edge_max<<<edgeBlocks, 256>>>(ei, E, N);
    edge_sum<<<edgeBlocks, 256>>>(ei, E, N);
    edge_agg256<<<aggBlocks, 256>>>(ei, E, N, h, y);

    // ---- layer 3 ----
    gemm_node3<<<nodeBlocks, 256>>>(y, W3, a_src3, a_dst3, b3, h3, out, N);
    edge_max<<<edgeBlocks, 256>>>(ei, E, N);
    edge_sum<<<edgeBlocks, 256>>>(ei, E, N);
    edge_agg10<<<edgeBlocks, 256>>>(ei, E, N, h3, out);
}

// round 3
// speedup vs baseline: 1.0706x; 1.0706x over previous
#include <cuda_runtime.h>
#include <cuda_bf16.h>
#include <cstdint>
#include <math.h>

// ---------------- problem constants ----------------
#define NMAX   50048          // nodes (50000, padded)
#define DH     256            // hidden dim
#define COUT   10             // output classes
#define EMAX   860064         // edges incl. self loops (800000 + 50000, padded)

typedef unsigned int u32;

// ---------------- device scratch (no allocations allowed) ----------------
__device__ float g_h [ (size_t)NMAX * DH ];   // GEMM output / gather source
__device__ float g_y [ (size_t)NMAX * DH ];   // aggregation target / next input
__device__ float g_h3[ (size_t)NMAX * COUT ];
__device__ float g_as[NMAX];
__device__ float g_ad[NMAX];
__device__ float g_m [NMAX];
__device__ float g_den[NMAX];
__device__ float g_e [EMAX];
__device__ float g_p [EMAX];
__device__ int   g_is64;

// ---------------- helpers ----------------
__device__ __forceinline__ void atomicMaxFloat(float* addr, float val) {
    if (val >= 0.0f) atomicMax((int*)addr, __float_as_int(val));
    else             atomicMin((unsigned int*)addr, (unsigned int)__float_as_int(val));
}

__device__ __forceinline__ void redAdd4(float* p, float4 v) {
    asm volatile("red.global.add.v4.f32 [%0], {%1,%2,%3,%4};"
                 :: "l"(p), "f"(v.x), "f"(v.y), "f"(v.z), "f"(v.w) : "memory");
}

__device__ __forceinline__ void get_edge(const void* ei, int E, int N, int i,
                                         int& s, int& d) {
    if (i < E) {
        if (g_is64) {
            const long long* p = (const long long*)ei;
            s = (int)p[i]; d = (int)p[E + i];
        } else {
            const int* p = (const int*)ei;
            s = p[i]; d = p[E + i];
        }
    } else {
        s = i - E; d = s;   // self loop
    }
}

// Detect whether edge_index is int64 or int32.
__global__ void detect_width_kernel(const int* ei2, int E) {
    __shared__ int any;
    if (threadIdx.x == 0) any = 0;
    __syncthreads();
    int limit = min(E, 2048);
    for (int j = threadIdx.x; j < limit; j += blockDim.x)
        if (ei2[2 * j + 1] != 0) any = 1;
    __syncthreads();
    if (threadIdx.x == 0) g_is64 = (any ? 0 : 1);
}

// ---------------- tf32 helpers ----------------
__device__ __forceinline__ u32 f2tf32(float x) {
    u32 u;
    asm("cvt.rna.tf32.f32 %0, %1;" : "=r"(u) : "f"(x));
    return u;
}

__device__ __forceinline__ void mma8(float* c,
                                     const u32* a, const u32* b) {
    asm volatile(
        "mma.sync.aligned.m16n8k8.row.col.f32.tf32.tf32.f32 "
        "{%0,%1,%2,%3},{%4,%5,%6,%7},{%8,%9},{%0,%1,%2,%3};"
        : "+f"(c[0]), "+f"(c[1]), "+f"(c[2]), "+f"(c[3])
        : "r"(a[0]), "r"(a[1]), "r"(a[2]), "r"(a[3]),
          "r"(b[0]), "r"(b[1]));
}

// ---------------- tensor-core GEMM: C[M,256] = act(A[M,256]) @ B[256,256] --
// 3xTF32 fp32 emulation. CTA tile 128x128, 8 warps, warp tile 32x64.
template<bool RELU>
__global__ void __launch_bounds__(256)
gemm_tc(const float* __restrict__ A, const float* __restrict__ B,
        float* __restrict__ C, int M) {
    const int K = 256, N = 256;
    __shared__ float Ash[128][20];
    __shared__ float Asl[128][20];
    __shared__ float Bsh[16][136];
    __shared__ float Bsl[16][136];

    const int tid = threadIdx.x;
    const int bm = blockIdx.y, bn = blockIdx.x;
    const int wid = tid >> 5, lane = tid & 31;
    const int wm = wid >> 1;              // 0..3 : M offset wm*32
    const int wn = wid & 1;               // 0..1 : N offset wn*64
    const int g = lane >> 2, tig = lane & 3;

    float acc[2][8][4];
#pragma unroll
    for (int mt = 0; mt < 2; mt++)
#pragma unroll
        for (int nt = 0; nt < 8; nt++)
#pragma unroll
            for (int r = 0; r < 4; r++) acc[mt][nt][r] = 0.0f;

    const int arow = tid >> 2;            // 0..63
    const int acol = (tid & 3) * 4;       // 0,4,8,12
    const int brow = tid >> 5;            // 0..7
    const int bcol = (tid & 31) * 4;      // 0..124

    for (int kc = 0; kc < K; kc += 16) {
        // load A tile 128x16, split into tf32 hi/lo
#pragma unroll
        for (int pass = 0; pass < 2; pass++) {
            int row = arow + pass * 64;
            int grow = bm * 128 + row;
            float4 v = make_float4(0, 0, 0, 0);
            if (grow < M)
                v = *(const float4*)(A + (size_t)grow * K + kc + acol);
            if (RELU) {
                v.x = fmaxf(v.x, 0.0f); v.y = fmaxf(v.y, 0.0f);
                v.z = fmaxf(v.z, 0.0f); v.w = fmaxf(v.w, 0.0f);
            }
            float e[4] = {v.x, v.y, v.z, v.w};
#pragma unroll
            for (int j = 0; j < 4; j++) {
                float hi = __uint_as_float(f2tf32(e[j]));
                Ash[row][acol + j] = hi;
                Asl[row][acol + j] = __uint_as_float(f2tf32(e[j] - hi));
            }
        }
        // load B tile 16x128, split
#pragma unroll
        for (int pass = 0; pass < 2; pass++) {
            int r = brow + pass * 8;
            float4 v = *(const float4*)(B + (size_t)(kc + r) * N + bn * 128 + bcol);
            float e[4] = {v.x, v.y, v.z, v.w};
#pragma unroll
            for (int j = 0; j < 4; j++) {
                float hi = __uint_as_float(f2tf32(e[j]));
                Bsh[r][bcol + j] = hi;
                Bsl[r][bcol + j] = __uint_as_float(f2tf32(e[j] - hi));
            }
        }
        __syncthreads();

#pragma unroll
        for (int k8 = 0; k8 < 16; k8 += 8) {
            u32 ah[2][4], al[2][4];
#pragma unroll
            for (int mt = 0; mt < 2; mt++) {
                int r0 = wm * 32 + mt * 16;
                ah[mt][0] = __float_as_uint(Ash[r0 + g][k8 + tig]);
                ah[mt][1] = __float_as_uint(Ash[r0 + g + 8][k8 + tig]);
                ah[mt][2] = __float_as_uint(Ash[r0 + g][k8 + tig + 4]);
                ah[mt][3] = __float_as_uint(Ash[r0 + g + 8][k8 + tig + 4]);
                al[mt][0] = __float_as_uint(Asl[r0 + g][k8 + tig]);
                al[mt][1] = __float_as_uint(Asl[r0 + g + 8][k8 + tig]);
                al[mt][2] = __float_as_uint(Asl[r0 + g][k8 + tig + 4]);
                al[mt][3] = __float_as_uint(Asl[r0 + g + 8][k8 + tig + 4]);
            }
            u32 bh[8][2], bl[8][2];
#pragma unroll
            for (int nt = 0; nt < 8; nt++) {
                int c0 = wn * 64 + nt * 8 + g;
                bh[nt][0] = __float_as_uint(Bsh[k8 + tig][c0]);
                bh[nt][1] = __float_as_uint(Bsh[k8 + tig + 4][c0]);
                bl[nt][0] = __float_as_uint(Bsl[k8 + tig][c0]);
                bl[nt][1] = __float_as_uint(Bsl[k8 + tig + 4][c0]);
            }
#pragma unroll
            for (int mt = 0; mt < 2; mt++)
#pragma unroll
                for (int nt = 0; nt < 8; nt++) {
                    mma8(acc[mt][nt], al[mt], bh[nt]);  // lo*hi
                    mma8(acc[mt][nt], ah[mt], bl[nt]);  // hi*lo
                    mma8(acc[mt][nt], ah[mt], bh[nt]);  // hi*hi
                }
        }
        __syncthreads();
    }

    // store C
#pragma unroll
    for (int mt = 0; mt < 2; mt++) {
        int r0 = bm * 128 + wm * 32 + mt * 16 + g;
#pragma unroll
        for (int nt = 0; nt < 8; nt++) {
            int col = bn * 128 + wn * 64 + nt * 8 + 2 * tig;
            if (r0 < M)
                *(float2*)(C + (size_t)r0 * N + col) =
                    make_float2(acc[mt][nt][0], acc[mt][nt][1]);
            if (r0 + 8 < M)
                *(float2*)(C + (size_t)(r0 + 8) * N + col) =
                    make_float2(acc[mt][nt][2], acc[mt][nt][3]);
        }
    }
}

// ---------------- per-node prep: alphas + init m/den + y-row = bias ----------------
__global__ void node_prep(const float* __restrict__ h,
                          const float* __restrict__ a_src,
                          const float* __restrict__ a_dst,
                          const float* __restrict__ b,
                          float* __restrict__ y, int N) {
    int n = (blockIdx.x * blockDim.x + threadIdx.x) >> 5;
    int lane = threadIdx.x & 31;
    if (n >= N) return;
    const float4* hr = (const float4*)(h + (size_t)n * DH);
    float4* yr = (float4*)(y + (size_t)n * DH);
    const float4* as4 = (const float4*)a_src;
    const float4* ad4 = (const float4*)a_dst;
    const float4* b4 = (const float4*)b;
    float ss = 0.0f, sd = 0.0f;
#pragma unroll
    for (int i = lane; i < DH / 4; i += 32) {
        float4 v = hr[i];
        float4 sa = as4[i];
        float4 da = ad4[i];
        ss += v.x * sa.x + v.y * sa.y + v.z * sa.z + v.w * sa.w;
        sd += v.x * da.x + v.y * da.y + v.z * da.z + v.w * da.w;
        yr[i] = b4[i];
    }
#pragma unroll
    for (int o = 16; o > 0; o >>= 1) {
        ss += __shfl_xor_sync(0xFFFFFFFFu, ss, o);
        sd += __shfl_xor_sync(0xFFFFFFFFu, sd, o);
    }
    if (lane == 0) {
        g_as[n] = ss;
        g_ad[n] = sd;
        g_m[n] = -INFINITY;
        g_den[n] = 0.0f;
    }
}

// ---------------- edge passes ----------------
__global__ void edge_max(const void* __restrict__ ei, int E, int N) {
    int i = blockIdx.x * blockDim.x + threadIdx.x;
    if (i >= E + N) return;
    int s, d;
    get_edge(ei, E, N, i, s, d);
    float v = g_as[s] + g_ad[d];
    v = v > 0.0f ? v : 0.2f * v;       // leaky_relu(0.2)
    g_e[i] = v;
    atomicMaxFloat(&g_m[d], v);
}

__global__ void edge_sum(const void* __restrict__ ei, int E, int N) {
    int i = blockIdx.x * blockDim.x + threadIdx.x;
    if (i >= E + N) return;
    int s, d;
    get_edge(ei, E, N, i, s, d);
    float p = __expf(g_e[i] - g_m[d]);
    g_p[i] = p;
    atomicAdd(&g_den[d], p);
}

__global__ void edge_agg256(const void* __restrict__ ei, int E, int N,
                            const float* __restrict__ h, float* __restrict__ y) {
    int gt = blockIdx.x * blockDim.x + threadIdx.x;
    int e = gt >> 5;
    int lane = gt & 31;
    if (e >= E + N) return;
    int s, d;
    get_edge(ei, E, N, e, s, d);
    float coeff = g_p[e] / g_den[d];
    const float4* hs = (const float4*)(h + (size_t)s * DH);
    float* yd = y + (size_t)d * DH;
#pragma unroll
    for (int i = lane; i < DH / 4; i += 32) {
        float4 v = hs[i];
        v.x *= coeff; v.y *= coeff; v.z *= coeff; v.w *= coeff;
        redAdd4(yd + i * 4, v);
    }
}

__global__ void edge_agg10(const void* __restrict__ ei, int E, int N,
                           const float* __restrict__ h3, float* __restrict__ out) {
    int e = blockIdx.x * blockDim.x + threadIdx.x;
    if (e >= E + N) return;
    int s, d;
    get_edge(ei, E, N, e, s, d);
    float coeff = g_p[e] / g_den[d];
    const float* hs = h3 + (size_t)s * COUT;
    float* od = out + (size_t)d * COUT;
#pragma unroll
    for (int c = 0; c < COUT; c++)
        atomicAdd(&od[c], coeff * hs[c]);
}

// ---------------- layer 3 GEMM (D_out = 10), warp per node ----------------
__global__ void gemm_node3(const float* __restrict__ in, const float* __restrict__ W,
                           const float* __restrict__ a_s, const float* __restrict__ a_d,
                           const float* __restrict__ b, float* __restrict__ h3,
                           float* __restrict__ out, int N) {
    int n = (blockIdx.x * blockDim.x + threadIdx.x) >> 5;
    int lane = threadIdx.x & 31;
    if (n >= N) return;
    float acc[COUT];
#pragma unroll
    for (int c = 0; c < COUT; c++) acc[c] = 0.0f;
    const float* xr = in + (size_t)n * DH;
#pragma unroll
    for (int i = 0; i < DH / 32; i++) {
        int k = lane + i * 32;
        float v = fmaxf(xr[k], 0.0f);                 // relu on input
#pragma unroll
        for (int c = 0; c < COUT; c++)
            acc[c] = fmaf(v, W[k * COUT + c], acc[c]);
    }
#pragma unroll
    for (int c = 0; c < COUT; c++)
#pragma unroll
        for (int o = 16; o > 0; o >>= 1)
            acc[c] += __shfl_xor_sync(0xFFFFFFFFu, acc[c], o);
    if (lane == 0) {
        float ss = 0.0f, sd = 0.0f;
#pragma unroll
        for (int c = 0; c < COUT; c++) {
            h3[(size_t)n * COUT + c] = acc[c];
            out[(size_t)n * COUT + c] = b[c];         // init output row with bias
            ss = fmaf(acc[c], a_s[c], ss);
            sd = fmaf(acc[c], a_d[c], sd);
        }
        g_as[n] = ss;
        g_ad[n] = sd;
        g_m[n] = -INFINITY;
        g_den[n] = 0.0f;
    }
}

// ---------------- host launcher ----------------
extern "C" void kernel_launch(void* const* d_in, const int* in_sizes, int n_in,
                              void* d_out, int out_size) {
    const float* x      = (const float*)d_in[0];
    const void*  ei     = d_in[1];
    const float* W1     = (const float*)d_in[2];
    const float* a_src1 = (const float*)d_in[3];
    const float* a_dst1 = (const float*)d_in[4];
    const float* b1     = (const float*)d_in[5];
    const float* W2     = (const float*)d_in[6];
    const float* a_src2 = (const float*)d_in[7];
    const float* a_dst2 = (const float*)d_in[8];
    const float* b2     = (const float*)d_in[9];
    const float* W3     = (const float*)d_in[10];
    const float* a_src3 = (const float*)d_in[11];
    const float* a_dst3 = (const float*)d_in[12];
    const float* b3     = (const float*)d_in[13];

    int N = in_sizes[0] / DH;      // 50000
    int E = in_sizes[1] / 2;       // 800000
    int ET = E + N;                // with self-loops

    float *h, *y, *h3;
    cudaGetSymbolAddress((void**)&h,  g_h);
    cudaGetSymbolAddress((void**)&y,  g_y);
    cudaGetSymbolAddress((void**)&h3, g_h3);
    float* out = (float*)d_out;

    detect_width_kernel<<<1, 256>>>((const int*)ei, E);

    dim3 ggrid(2, (N + 127) / 128);
    int nodeBlocks = (N * 32 + 255) / 256;
    int edgeBlocks = (ET + 255) / 256;
    int aggBlocks  = ((size_t)ET * 32 + 255) / 256;

    // ---- layer 1 ----
    gemm_tc<false><<<ggrid, 256>>>(x, W1, h, N);
    node_prep<<<nodeBlocks, 256>>>(h, a_src1, a_dst1, b1, y, N);
    edge_max<<<edgeBlocks, 256>>>(ei, E, N);
    edge_sum<<<edgeBlocks, 256>>>(ei, E, N);
    edge_agg256<<<aggBlocks, 256>>>(ei, E, N, h, y);

    // ---- layer 2 ----
    gemm_tc<true><<<ggrid, 256>>>(y, W2, h, N);
    node_prep<<<nodeBlocks, 256>>>(h, a_src2, a_dst2, b2, y, N);
    edge_max<<<edgeBlocks, 256>>>(ei, E, N);
    edge_sum<<<edgeBlocks, 256>>>(ei, E, N);
    edge_agg256<<<aggBlocks, 256>>>(ei, E, N, h, y);

    // ---- layer 3 ----
    gemm_node3<<<nodeBlocks, 256>>>(y, W3, a_src3, a_dst3, b3, h3, out, N);
    edge_max<<<edgeBlocks, 256>>>(ei, E, N);
    edge_sum<<<edgeBlocks, 256>>>(ei, E, N);
    edge_agg10<<<edgeBlocks, 256>>>(ei, E, N, h3, out);
}

// round 4
// speedup vs baseline: 1.3741x; 1.2835x over previous
#include <cuda_runtime.h>
#include <cuda_bf16.h>
#include <cstdint>
#include <math.h>

// ---------------- problem constants ----------------
#define NMAX   50048          // nodes (50000, padded)
#define DH     256            // hidden dim
#define COUT   10             // output classes
#define EMAX   860064         // edges incl. self loops (800000 + 50000, padded)

typedef unsigned int u32;

// ---------------- device scratch (no allocations allowed) ----------------
__device__ float g_h [ (size_t)NMAX * DH ];   // GEMM output / gather source
__device__ float g_y [ (size_t)NMAX * DH ];   // aggregation target / next input
__device__ float g_h3[ (size_t)NMAX * COUT ];
__device__ float g_as[NMAX];
__device__ float g_ad[NMAX];
__device__ int   g_cnt[NMAX];                 // histogram
__device__ int   g_row[NMAX + 1];             // CSR row offsets
__device__ int   g_cur[NMAX];                 // scatter cursors
__device__ int   g_col[EMAX];                 // CSR: src node per edge slot
__device__ int   g_is64;

// ---------------- helpers ----------------
__device__ __forceinline__ void get_edge(const void* ei, int E, int N, int i,
                                         int& s, int& d) {
    if (i < E) {
        if (g_is64) {
            const long long* p = (const long long*)ei;
            s = (int)p[i]; d = (int)p[E + i];
        } else {
            const int* p = (const int*)ei;
            s = p[i]; d = p[E + i];
        }
    } else {
        s = i - E; d = s;   // self loop
    }
}

// Detect whether edge_index is int64 or int32.
__global__ void detect_width_kernel(const int* ei2, int E) {
    __shared__ int any;
    if (threadIdx.x == 0) any = 0;
    __syncthreads();
    int limit = min(E, 2048);
    for (int j = threadIdx.x; j < limit; j += blockDim.x)
        if (ei2[2 * j + 1] != 0) any = 1;
    __syncthreads();
    if (threadIdx.x == 0) g_is64 = (any ? 0 : 1);
}

// ---------------- CSR build ----------------
__global__ void hist_kernel(const void* __restrict__ ei, int E, int N) {
    int i = blockIdx.x * blockDim.x + threadIdx.x;
    if (i >= E + N) return;
    int s, d;
    get_edge(ei, E, N, i, s, d);
    atomicAdd(&g_cnt[d], 1);
}

__global__ void scan_kernel(int N) {
    __shared__ int sh[1024];
    int t = threadIdx.x;
    int chunk = (N + 1023) >> 10;
    int b = t * chunk, e = min(b + chunk, N);
    int sum = 0;
    for (int i = b; i < e; i++) sum += g_cnt[i];
    sh[t] = sum;
    __syncthreads();
#pragma unroll
    for (int o = 1; o < 1024; o <<= 1) {
        int v = 0;
        if (t >= o) v = sh[t - o];
        __syncthreads();
        if (t >= o) sh[t] += v;
        __syncthreads();
    }
    int run = (t > 0) ? sh[t - 1] : 0;
    for (int i = b; i < e; i++) {
        g_row[i] = run;
        g_cur[i] = run;
        run += g_cnt[i];
    }
    if (t == 1023) g_row[N] = sh[1023];
}

__global__ void scatter_kernel(const void* __restrict__ ei, int E, int N) {
    int i = blockIdx.x * blockDim.x + threadIdx.x;
    if (i >= E + N) return;
    int s, d;
    get_edge(ei, E, N, i, s, d);
    int pos = atomicAdd(&g_cur[d], 1);
    g_col[pos] = s;
}

// ---------------- tf32 helpers ----------------
__device__ __forceinline__ u32 f2tf32(float x) {
    u32 u;
    asm("cvt.rna.tf32.f32 %0, %1;" : "=r"(u) : "f"(x));
    return u;
}

__device__ __forceinline__ void mma8(float* c,
                                     const u32* a, const u32* b) {
    asm volatile(
        "mma.sync.aligned.m16n8k8.row.col.f32.tf32.tf32.f32 "
        "{%0,%1,%2,%3},{%4,%5,%6,%7},{%8,%9},{%0,%1,%2,%3};"
        : "+f"(c[0]), "+f"(c[1]), "+f"(c[2]), "+f"(c[3])
        : "r"(a[0]), "r"(a[1]), "r"(a[2]), "r"(a[3]),
          "r"(b[0]), "r"(b[1]));
}

// ---------------- tensor-core GEMM: C[M,256] = act(A[M,256]) @ B[256,256] --
// 3xTF32 fp32 emulation. CTA tile 128x128, 8 warps, warp tile 32x64.
template<bool RELU>
__global__ void __launch_bounds__(256)
gemm_tc(const float* __restrict__ A, const float* __restrict__ B,
        float* __restrict__ C, int M) {
    const int K = 256, N = 256;
    __shared__ float Ash[128][20];
    __shared__ float Asl[128][20];
    __shared__ float Bsh[16][136];
    __shared__ float Bsl[16][136];

    const int tid = threadIdx.x;
    const int bm = blockIdx.y, bn = blockIdx.x;
    const int wid = tid >> 5, lane = tid & 31;
    const int wm = wid >> 1;              // 0..3 : M offset wm*32
    const int wn = wid & 1;               // 0..1 : N offset wn*64
    const int g = lane >> 2, tig = lane & 3;

    float acc[2][8][4];
#pragma unroll
    for (int mt = 0; mt < 2; mt++)
#pragma unroll
        for (int nt = 0; nt < 8; nt++)
#pragma unroll
            for (int r = 0; r < 4; r++) acc[mt][nt][r] = 0.0f;

    const int arow = tid >> 2;            // 0..63
    const int acol = (tid & 3) * 4;       // 0,4,8,12
    const int brow = tid >> 5;            // 0..7
    const int bcol = (tid & 31) * 4;      // 0..124

    for (int kc = 0; kc < K; kc += 16) {
#pragma unroll
        for (int pass = 0; pass < 2; pass++) {
            int row = arow + pass * 64;
            int grow = bm * 128 + row;
            float4 v = make_float4(0, 0, 0, 0);
            if (grow < M)
                v = *(const float4*)(A + (size_t)grow * K + kc + acol);
            if (RELU) {
                v.x = fmaxf(v.x, 0.0f); v.y = fmaxf(v.y, 0.0f);
                v.z = fmaxf(v.z, 0.0f); v.w = fmaxf(v.w, 0.0f);
            }
            float e[4] = {v.x, v.y, v.z, v.w};
#pragma unroll
            for (int j = 0; j < 4; j++) {
                float hi = __uint_as_float(f2tf32(e[j]));
                Ash[row][acol + j] = hi;
                Asl[row][acol + j] = __uint_as_float(f2tf32(e[j] - hi));
            }
        }
#pragma unroll
        for (int pass = 0; pass < 2; pass++) {
            int r = brow + pass * 8;
            float4 v = *(const float4*)(B + (size_t)(kc + r) * N + bn * 128 + bcol);
            float e[4] = {v.x, v.y, v.z, v.w};
#pragma unroll
            for (int j = 0; j < 4; j++) {
                float hi = __uint_as_float(f2tf32(e[j]));
                Bsh[r][bcol + j] = hi;
                Bsl[r][bcol + j] = __uint_as_float(f2tf32(e[j] - hi));
            }
        }
        __syncthreads();

#pragma unroll
        for (int k8 = 0; k8 < 16; k8 += 8) {
            u32 ah[2][4], al[2][4];
#pragma unroll
            for (int mt = 0; mt < 2; mt++) {
                int r0 = wm * 32 + mt * 16;
                ah[mt][0] = __float_as_uint(Ash[r0 + g][k8 + tig]);
                ah[mt][1] = __float_as_uint(Ash[r0 + g + 8][k8 + tig]);
                ah[mt][2] = __float_as_uint(Ash[r0 + g][k8 + tig + 4]);
                ah[mt][3] = __float_as_uint(Ash[r0 + g + 8][k8 + tig + 4]);
                al[mt][0] = __float_as_uint(Asl[r0 + g][k8 + tig]);
                al[mt][1] = __float_as_uint(Asl[r0 + g + 8][k8 + tig]);
                al[mt][2] = __float_as_uint(Asl[r0 + g][k8 + tig + 4]);
                al[mt][3] = __float_as_uint(Asl[r0 + g + 8][k8 + tig + 4]);
            }
            u32 bh[8][2], bl[8][2];
#pragma unroll
            for (int nt = 0; nt < 8; nt++) {
                int c0 = wn * 64 + nt * 8 + g;
                bh[nt][0] = __float_as_uint(Bsh[k8 + tig][c0]);
                bh[nt][1] = __float_as_uint(Bsh[k8 + tig + 4][c0]);
                bl[nt][0] = __float_as_uint(Bsl[k8 + tig][c0]);
                bl[nt][1] = __float_as_uint(Bsl[k8 + tig + 4][c0]);
            }
#pragma unroll
            for (int mt = 0; mt < 2; mt++)
#pragma unroll
                for (int nt = 0; nt < 8; nt++) {
                    mma8(acc[mt][nt], al[mt], bh[nt]);  // lo*hi
                    mma8(acc[mt][nt], ah[mt], bl[nt]);  // hi*lo
                    mma8(acc[mt][nt], ah[mt], bh[nt]);  // hi*hi
                }
        }
        __syncthreads();
    }

#pragma unroll
    for (int mt = 0; mt < 2; mt++) {
        int r0 = bm * 128 + wm * 32 + mt * 16 + g;
#pragma unroll
        for (int nt = 0; nt < 8; nt++) {
            int col = bn * 128 + wn * 64 + nt * 8 + 2 * tig;
            if (r0 < M)
                *(float2*)(C + (size_t)r0 * N + col) =
                    make_float2(acc[mt][nt][0], acc[mt][nt][1]);
            if (r0 + 8 < M)
                *(float2*)(C + (size_t)(r0 + 8) * N + col) =
                    make_float2(acc[mt][nt][2], acc[mt][nt][3]);
        }
    }
}

// ---------------- per-node alphas (warp per node) ----------------
__global__ void node_alpha(const float* __restrict__ h,
                           const float* __restrict__ a_src,
                           const float* __restrict__ a_dst, int N) {
    int n = (blockIdx.x * blockDim.x + threadIdx.x) >> 5;
    int lane = threadIdx.x & 31;
    if (n >= N) return;
    const float4* hr = (const float4*)(h + (size_t)n * DH);
    const float4* as4 = (const float4*)a_src;
    const float4* ad4 = (const float4*)a_dst;
    float ss = 0.0f, sd = 0.0f;
#pragma unroll
    for (int i = lane; i < DH / 4; i += 32) {
        float4 v = hr[i];
        float4 sa = as4[i];
        float4 da = ad4[i];
        ss += v.x * sa.x + v.y * sa.y + v.z * sa.z + v.w * sa.w;
        sd += v.x * da.x + v.y * da.y + v.z * da.z + v.w * da.w;
    }
#pragma unroll
    for (int o = 16; o > 0; o >>= 1) {
        ss += __shfl_xor_sync(0xFFFFFFFFu, ss, o);
        sd += __shfl_xor_sync(0xFFFFFFFFu, sd, o);
    }
    if (lane == 0) {
        g_as[n] = ss;
        g_ad[n] = sd;
    }
}

// ---------------- fused softmax + aggregation, warp per dst node ----------------
__device__ __forceinline__ float leaky(float v) {
    return v > 0.0f ? v : 0.2f * v;
}

__global__ void __launch_bounds__(256)
fused_agg256(const float* __restrict__ h, const float* __restrict__ bias,
             float* __restrict__ y, int N) {
    int n = (blockIdx.x * blockDim.x + threadIdx.x) >> 5;
    int lane = threadIdx.x & 31;
    if (n >= N) return;
    int beg = g_row[n], end = g_row[n + 1];
    float ad = g_ad[n];

    // pass 1: segment max
    float m = -INFINITY;
    for (int j = beg + lane; j < end; j += 32)
        m = fmaxf(m, leaky(g_as[g_col[j]] + ad));
#pragma unroll
    for (int o = 16; o > 0; o >>= 1)
        m = fmaxf(m, __shfl_xor_sync(0xFFFFFFFFu, m, o));

    // pass 2: denominator
    float den = 0.0f;
    for (int j = beg + lane; j < end; j += 32)
        den += __expf(leaky(g_as[g_col[j]] + ad) - m);
#pragma unroll
    for (int o = 16; o > 0; o >>= 1)
        den += __shfl_xor_sync(0xFFFFFFFFu, den, o);
    float inv = 1.0f / den;

    // pass 3: accumulate  (lane owns 8 contiguous floats of the 256-dim row)
    float4 acc0 = make_float4(0, 0, 0, 0);
    float4 acc1 = make_float4(0, 0, 0, 0);
    for (int j = beg; j < end; j++) {
        int s = g_col[j];                       // broadcast
        float p = __expf(leaky(g_as[s] + ad) - m);
        const float4* hr = (const float4*)(h + (size_t)s * DH) + lane * 2;
        float4 v0 = hr[0], v1 = hr[1];
        acc0.x = fmaf(p, v0.x, acc0.x); acc0.y = fmaf(p, v0.y, acc0.y);
        acc0.z = fmaf(p, v0.z, acc0.z); acc0.w = fmaf(p, v0.w, acc0.w);
        acc1.x = fmaf(p, v1.x, acc1.x); acc1.y = fmaf(p, v1.y, acc1.y);
        acc1.z = fmaf(p, v1.z, acc1.z); acc1.w = fmaf(p, v1.w, acc1.w);
    }
    float4 b0 = ((const float4*)bias)[lane * 2];
    float4 b1 = ((const float4*)bias)[lane * 2 + 1];
    float4 o0 = make_float4(fmaf(acc0.x, inv, b0.x), fmaf(acc0.y, inv, b0.y),
                            fmaf(acc0.z, inv, b0.z), fmaf(acc0.w, inv, b0.w));
    float4 o1 = make_float4(fmaf(acc1.x, inv, b1.x), fmaf(acc1.y, inv, b1.y),
                            fmaf(acc1.z, inv, b1.z), fmaf(acc1.w, inv, b1.w));
    float4* yr = (float4*)(y + (size_t)n * DH) + lane * 2;
    yr[0] = o0;
    yr[1] = o1;
}

__global__ void __launch_bounds__(256)
fused_agg10(const float* __restrict__ h3, const float* __restrict__ bias,
            float* __restrict__ out, int N) {
    int n = (blockIdx.x * blockDim.x + threadIdx.x) >> 5;
    int lane = threadIdx.x & 31;
    if (n >= N) return;
    int beg = g_row[n], end = g_row[n + 1];
    float ad = g_ad[n];

    float m = -INFINITY;
    for (int j = beg + lane; j < end; j += 32)
        m = fmaxf(m, leaky(g_as[g_col[j]] + ad));
#pragma unroll
    for (int o = 16; o > 0; o >>= 1)
        m = fmaxf(m, __shfl_xor_sync(0xFFFFFFFFu, m, o));

    float den = 0.0f;
    for (int j = beg + lane; j < end; j += 32)
        den += __expf(leaky(g_as[g_col[j]] + ad) - m);
#pragma unroll
    for (int o = 16; o > 0; o >>= 1)
        den += __shfl_xor_sync(0xFFFFFFFFu, den, o);
    float inv = 1.0f / den;

    float acc = 0.0f;
    for (int j = beg; j < end; j++) {
        int s = g_col[j];
        float p = __expf(leaky(g_as[s] + ad) - m);
        if (lane < COUT)
            acc = fmaf(p, h3[(size_t)s * COUT + lane], acc);
    }
    if (lane < COUT)
        out[(size_t)n * COUT + lane] = fmaf(acc, inv, bias[lane]);
}

// ---------------- layer 3 GEMM (D_out = 10), warp per node ----------------
__global__ void gemm_node3(const float* __restrict__ in, const float* __restrict__ W,
                           const float* __restrict__ a_s, const float* __restrict__ a_d,
                           float* __restrict__ h3, int N) {
    int n = (blockIdx.x * blockDim.x + threadIdx.x) >> 5;
    int lane = threadIdx.x & 31;
    if (n >= N) return;
    float acc[COUT];
#pragma unroll
    for (int c = 0; c < COUT; c++) acc[c] = 0.0f;
    const float* xr = in + (size_t)n * DH;
#pragma unroll
    for (int i = 0; i < DH / 32; i++) {
        int k = lane + i * 32;
        float v = fmaxf(xr[k], 0.0f);                 // relu on input
#pragma unroll
        for (int c = 0; c < COUT; c++)
            acc[c] = fmaf(v, W[k * COUT + c], acc[c]);
    }
#pragma unroll
    for (int c = 0; c < COUT; c++)
#pragma unroll
        for (int o = 16; o > 0; o >>= 1)
            acc[c] += __shfl_xor_sync(0xFFFFFFFFu, acc[c], o);
    if (lane == 0) {
        float ss = 0.0f, sd = 0.0f;
#pragma unroll
        for (int c = 0; c < COUT; c++) {
            h3[(size_t)n * COUT + c] = acc[c];
            ss = fmaf(acc[c], a_s[c], ss);
            sd = fmaf(acc[c], a_d[c], sd);
        }
        g_as[n] = ss;
        g_ad[n] = sd;
    }
}

// ---------------- host launcher ----------------
extern "C" void kernel_launch(void* const* d_in, const int* in_sizes, int n_in,
                              void* d_out, int out_size) {
    const float* x      = (const float*)d_in[0];
    const void*  ei     = d_in[1];
    const float* W1     = (const float*)d_in[2];
    const float* a_src1 = (const float*)d_in[3];
    const float* a_dst1 = (const float*)d_in[4];
    const float* b1     = (const float*)d_in[5];
    const float* W2     = (const float*)d_in[6];
    const float* a_src2 = (const float*)d_in[7];
    const float* a_dst2 = (const float*)d_in[8];
    const float* b2     = (const float*)d_in[9];
    const float* W3     = (const float*)d_in[10];
    const float* a_src3 = (const float*)d_in[11];
    const float* a_dst3 = (const float*)d_in[12];
    const float* b3     = (const float*)d_in[13];

    int N = in_sizes[0] / DH;      // 50000
    int E = in_sizes[1] / 2;       // 800000
    int ET = E + N;                // with self-loops

    float *h, *y, *h3;
    int* cnt;
    cudaGetSymbolAddress((void**)&h,   g_h);
    cudaGetSymbolAddress((void**)&y,   g_y);
    cudaGetSymbolAddress((void**)&h3,  g_h3);
    cudaGetSymbolAddress((void**)&cnt, g_cnt);
    float* out = (float*)d_out;

    detect_width_kernel<<<1, 256>>>((const int*)ei, E);

    // ---- CSR build (reused by all 3 layers) ----
    cudaMemsetAsync(cnt, 0, (size_t)N * sizeof(int));
    int edgeBlocks = (ET + 255) / 256;
    hist_kernel<<<edgeBlocks, 256>>>(ei, E, N);
    scan_kernel<<<1, 1024>>>(N);
    scatter_kernel<<<edgeBlocks, 256>>>(ei, E, N);

    dim3 ggrid(2, (N + 127) / 128);
    int nodeBlocks = (N * 32 + 255) / 256;

    // ---- layer 1 ----
    gemm_tc<false><<<ggrid, 256>>>(x, W1, h, N);
    node_alpha<<<nodeBlocks, 256>>>(h, a_src1, a_dst1, N);
    fused_agg256<<<nodeBlocks, 256>>>(h, b1, y, N);

    // ---- layer 2 ----
    gemm_tc<true><<<ggrid, 256>>>(y, W2, h, N);
    node_alpha<<<nodeBlocks, 256>>>(h, a_src2, a_dst2, N);
    fused_agg256<<<nodeBlocks, 256>>>(h, b2, y, N);

    // ---- layer 3 ----
    gemm_node3<<<nodeBlocks, 256>>>(y, W3, a_src3, a_dst3, h3, N);
    fused_agg10<<<nodeBlocks, 256>>>(h3, b3, out, N);
}

// round 5
// speedup vs baseline: 1.6906x; 1.2304x over previous
#include <cuda_runtime.h>
#include <cuda_bf16.h>
#include <cstdint>
#include <math.h>

// ---------------- problem constants ----------------
#define NMAX   50048          // nodes (50000, padded)
#define DH     256            // hidden dim
#define COUT   10             // output classes
#define EMAX   860064         // edges incl. self loops (800000 + 50000, padded)

typedef unsigned int u32;

// ---------------- device scratch (no allocations allowed) ----------------
__device__ float g_h [ (size_t)NMAX * DH ];   // GEMM output / gather source
__device__ float g_y [ (size_t)NMAX * DH ];   // aggregation target / next input
__device__ float g_h3[ (size_t)NMAX * COUT ];
__device__ float g_as[NMAX];
__device__ float g_ad[NMAX];
__device__ int   g_cnt[NMAX];                 // histogram
__device__ int   g_row[NMAX + 1];             // CSR row offsets
__device__ int   g_cur[NMAX];                 // scatter cursors
__device__ int   g_col[EMAX];                 // CSR: src node per edge slot
__device__ int   g_is64;

// ---------------- helpers ----------------
__device__ __forceinline__ void get_edge(const void* ei, int E, int N, int i,
                                         int& s, int& d) {
    if (i < E) {
        if (g_is64) {
            const long long* p = (const long long*)ei;
            s = (int)p[i]; d = (int)p[E + i];
        } else {
            const int* p = (const int*)ei;
            s = p[i]; d = p[E + i];
        }
    } else {
        s = i - E; d = s;   // self loop
    }
}

// Detect whether edge_index is int64 or int32.
__global__ void detect_width_kernel(const int* ei2, int E) {
    __shared__ int any;
    if (threadIdx.x == 0) any = 0;
    __syncthreads();
    int limit = min(E, 2048);
    for (int j = threadIdx.x; j < limit; j += blockDim.x)
        if (ei2[2 * j + 1] != 0) any = 1;
    __syncthreads();
    if (threadIdx.x == 0) g_is64 = (any ? 0 : 1);
}

// ---------------- CSR build ----------------
__global__ void hist_kernel(const void* __restrict__ ei, int E, int N) {
    int i = blockIdx.x * blockDim.x + threadIdx.x;
    if (i >= E + N) return;
    int s, d;
    get_edge(ei, E, N, i, s, d);
    atomicAdd(&g_cnt[d], 1);
}

__global__ void scan_kernel(int N) {
    __shared__ int sh[1024];
    int t = threadIdx.x;
    int chunk = (N + 1023) >> 10;
    int b = t * chunk, e = min(b + chunk, N);
    int sum = 0;
    for (int i = b; i < e; i++) sum += g_cnt[i];
    sh[t] = sum;
    __syncthreads();
#pragma unroll
    for (int o = 1; o < 1024; o <<= 1) {
        int v = 0;
        if (t >= o) v = sh[t - o];
        __syncthreads();
        if (t >= o) sh[t] += v;
        __syncthreads();
    }
    int run = (t > 0) ? sh[t - 1] : 0;
    for (int i = b; i < e; i++) {
        g_row[i] = run;
        g_cur[i] = run;
        run += g_cnt[i];
    }
    if (t == 1023) g_row[N] = sh[1023];
}

__global__ void scatter_kernel(const void* __restrict__ ei, int E, int N) {
    int i = blockIdx.x * blockDim.x + threadIdx.x;
    if (i >= E + N) return;
    int s, d;
    get_edge(ei, E, N, i, s, d);
    int pos = atomicAdd(&g_cur[d], 1);
    g_col[pos] = s;
}

// ---------------- bf16 mma helper ----------------
__device__ __forceinline__ void mma16(float* c, const u32* a, const u32* b) {
    asm volatile(
        "mma.sync.aligned.m16n8k16.row.col.f32.bf16.bf16.f32 "
        "{%0,%1,%2,%3},{%4,%5,%6,%7},{%8,%9},{%0,%1,%2,%3};"
        : "+f"(c[0]), "+f"(c[1]), "+f"(c[2]), "+f"(c[3])
        : "r"(a[0]), "r"(a[1]), "r"(a[2]), "r"(a[3]),
          "r"(b[0]), "r"(b[1]));
}

// ---------------- tensor-core GEMM: C[M,256] = act(A[M,256]) @ B[256,256] --
// bf16 hi/lo fp32 emulation (3x bf16 m16n8k16).
// CTA tile 128x128, 8 warps, warp tile 32x64, K-chunk 32.
template<bool RELU>
__global__ void __launch_bounds__(256)
gemm_tc(const float* __restrict__ A, const float* __restrict__ B,
        float* __restrict__ C, int M) {
    const int K = 256, N = 256;
    // pairs along K: Ash[row][kk] = {A[row][2kk], A[row][2kk+1]}
    __shared__ __nv_bfloat162 Ash[128][17];   // 16 pairs + 1 pad
    __shared__ __nv_bfloat162 Asl[128][17];
    __shared__ __nv_bfloat162 Bsh[16][136];   // [kk][col], pad 136
    __shared__ __nv_bfloat162 Bsl[16][136];

    const int tid = threadIdx.x;
    const int bm = blockIdx.y, bn = blockIdx.x;
    const int wid = tid >> 5, lane = tid & 31;
    const int wm = wid >> 1;              // 0..3 : M offset wm*32
    const int wn = wid & 1;               // 0..1 : N offset wn*64
    const int g = lane >> 2, tig = lane & 3;

    float acc[2][8][4];
#pragma unroll
    for (int mt = 0; mt < 2; mt++)
#pragma unroll
        for (int nt = 0; nt < 8; nt++)
#pragma unroll
            for (int r = 0; r < 4; r++) acc[mt][nt][r] = 0.0f;

    for (int kc = 0; kc < K; kc += 32) {
        // ---- load A tile 128x32 fp32 -> bf16 hi/lo ----
#pragma unroll
        for (int i = 0; i < 4; i++) {
            int idx = tid + i * 256;        // 0..1023
            int row = idx >> 3;             // 0..127
            int c4  = idx & 7;              // 0..7 (float4 index)
            int grow = bm * 128 + row;
            float4 v = make_float4(0, 0, 0, 0);
            if (grow < M)
                v = *(const float4*)(A + (size_t)grow * K + kc + c4 * 4);
            if (RELU) {
                v.x = fmaxf(v.x, 0.0f); v.y = fmaxf(v.y, 0.0f);
                v.z = fmaxf(v.z, 0.0f); v.w = fmaxf(v.w, 0.0f);
            }
            float e[4] = {v.x, v.y, v.z, v.w};
            __nv_bfloat16* ah = (__nv_bfloat16*)&Ash[row][0];
            __nv_bfloat16* al = (__nv_bfloat16*)&Asl[row][0];
#pragma unroll
            for (int j = 0; j < 4; j++) {
                int k = c4 * 4 + j;
                __nv_bfloat16 hb = __float2bfloat16(e[j]);
                float hf = __bfloat162float(hb);
                ah[k] = hb;
                al[k] = __float2bfloat16(e[j] - hf);
            }
        }
        // ---- load B tile 32x128 fp32 -> bf16 hi/lo, k-pair packed ----
#pragma unroll
        for (int i = 0; i < 4; i++) {
            int idx = tid + i * 256;
            int r  = idx >> 5;              // 0..31 (k within chunk)
            int c4 = idx & 31;              // 0..31 (float4 index)
            float4 v = *(const float4*)(B + (size_t)(kc + r) * N + bn * 128 + c4 * 4);
            float e[4] = {v.x, v.y, v.z, v.w};
            int kk = r >> 1, par = r & 1;
#pragma unroll
            for (int j = 0; j < 4; j++) {
                int col = c4 * 4 + j;
                __nv_bfloat16 hb = __float2bfloat16(e[j]);
                float hf = __bfloat162float(hb);
                ((__nv_bfloat16*)&Bsh[kk][col])[par] = hb;
                ((__nv_bfloat16*)&Bsl[kk][col])[par] = __float2bfloat16(e[j] - hf);
            }
        }
        __syncthreads();

#pragma unroll
        for (int ks = 0; ks < 2; ks++) {
            int kb = ks * 8;                // pair-index base (k base = 16*ks)
            u32 ah[2][4], al[2][4];
#pragma unroll
            for (int mt = 0; mt < 2; mt++) {
                int r0 = wm * 32 + mt * 16;
                ah[mt][0] = *(const u32*)&Ash[r0 + g][kb + tig];
                ah[mt][1] = *(const u32*)&Ash[r0 + g + 8][kb + tig];
                ah[mt][2] = *(const u32*)&Ash[r0 + g][kb + tig + 4];
                ah[mt][3] = *(const u32*)&Ash[r0 + g + 8][kb + tig + 4];
                al[mt][0] = *(const u32*)&Asl[r0 + g][kb + tig];
                al[mt][1] = *(const u32*)&Asl[r0 + g + 8][kb + tig];
                al[mt][2] = *(const u32*)&Asl[r0 + g][kb + tig + 4];
                al[mt][3] = *(const u32*)&Asl[r0 + g + 8][kb + tig + 4];
            }
            u32 bh[8][2], bl[8][2];
#pragma unroll
            for (int nt = 0; nt < 8; nt++) {
                int c0 = wn * 64 + nt * 8 + g;
                bh[nt][0] = *(const u32*)&Bsh[kb + tig][c0];
                bh[nt][1] = *(const u32*)&Bsh[kb + tig + 4][c0];
                bl[nt][0] = *(const u32*)&Bsl[kb + tig][c0];
                bl[nt][1] = *(const u32*)&Bsl[kb + tig + 4][c0];
            }
#pragma unroll
            for (int mt = 0; mt < 2; mt++)
#pragma unroll
                for (int nt = 0; nt < 8; nt++) {
                    mma16(acc[mt][nt], al[mt], bh[nt]);  // lo*hi
                    mma16(acc[mt][nt], ah[mt], bl[nt]);  // hi*lo
                    mma16(acc[mt][nt], ah[mt], bh[nt]);  // hi*hi
                }
        }
        __syncthreads();
    }

    // ---- store C ----
#pragma unroll
    for (int mt = 0; mt < 2; mt++) {
        int r0 = bm * 128 + wm * 32 + mt * 16 + g;
#pragma unroll
        for (int nt = 0; nt < 8; nt++) {
            int col = bn * 128 + wn * 64 + nt * 8 + 2 * tig;
            if (r0 < M)
                *(float2*)(C + (size_t)r0 * N + col) =
                    make_float2(acc[mt][nt][0], acc[mt][nt][1]);
            if (r0 + 8 < M)
                *(float2*)(C + (size_t)(r0 + 8) * N + col) =
                    make_float2(acc[mt][nt][2], acc[mt][nt][3]);
        }
    }
}

// ---------------- per-node alphas (warp per node) ----------------
__global__ void node_alpha(const float* __restrict__ h,
                           const float* __restrict__ a_src,
                           const float* __restrict__ a_dst, int N) {
    int n = (blockIdx.x * blockDim.x + threadIdx.x) >> 5;
    int lane = threadIdx.x & 31;
    if (n >= N) return;
    const float4* hr = (const float4*)(h + (size_t)n * DH);
    const float4* as4 = (const float4*)a_src;
    const float4* ad4 = (const float4*)a_dst;
    float ss = 0.0f, sd = 0.0f;
#pragma unroll
    for (int i = lane; i < DH / 4; i += 32) {
        float4 v = hr[i];
        float4 sa = as4[i];
        float4 da = ad4[i];
        ss += v.x * sa.x + v.y * sa.y + v.z * sa.z + v.w * sa.w;
        sd += v.x * da.x + v.y * da.y + v.z * da.z + v.w * da.w;
    }
#pragma unroll
    for (int o = 16; o > 0; o >>= 1) {
        ss += __shfl_xor_sync(0xFFFFFFFFu, ss, o);
        sd += __shfl_xor_sync(0xFFFFFFFFu, sd, o);
    }
    if (lane == 0) {
        g_as[n] = ss;
        g_ad[n] = sd;
    }
}

// ---------------- fused softmax + aggregation, warp per dst node ----------------
__device__ __forceinline__ float leaky(float v) {
    return v > 0.0f ? v : 0.2f * v;
}

__global__ void __launch_bounds__(256)
fused_agg256(const float* __restrict__ h, const float* __restrict__ bias,
             float* __restrict__ y, int N) {
    int n = (blockIdx.x * blockDim.x + threadIdx.x) >> 5;
    int lane = threadIdx.x & 31;
    if (n >= N) return;
    int beg = g_row[n], end = g_row[n + 1];
    float ad = g_ad[n];

    // pass 1: segment max
    float m = -INFINITY;
    for (int j = beg + lane; j < end; j += 32)
        m = fmaxf(m, leaky(g_as[g_col[j]] + ad));
#pragma unroll
    for (int o = 16; o > 0; o >>= 1)
        m = fmaxf(m, __shfl_xor_sync(0xFFFFFFFFu, m, o));

    // pass 2: denominator
    float den = 0.0f;
    for (int j = beg + lane; j < end; j += 32)
        den += __expf(leaky(g_as[g_col[j]] + ad) - m);
#pragma unroll
    for (int o = 16; o > 0; o >>= 1)
        den += __shfl_xor_sync(0xFFFFFFFFu, den, o);
    float inv = 1.0f / den;

    // pass 3: accumulate  (lane owns 8 contiguous floats of the 256-dim row)
    float4 acc0 = make_float4(0, 0, 0, 0);
    float4 acc1 = make_float4(0, 0, 0, 0);
    for (int j = beg; j < end; j++) {
        int s = g_col[j];                       // broadcast
        float p = __expf(leaky(g_as[s] + ad) - m);
        const float4* hr = (const float4*)(h + (size_t)s * DH) + lane * 2;
        float4 v0 = hr[0], v1 = hr[1];
        acc0.x = fmaf(p, v0.x, acc0.x); acc0.y = fmaf(p, v0.y, acc0.y);
        acc0.z = fmaf(p, v0.z, acc0.z); acc0.w = fmaf(p, v0.w, acc0.w);
        acc1.x = fmaf(p, v1.x, acc1.x); acc1.y = fmaf(p, v1.y, acc1.y);
        acc1.z = fmaf(p, v1.z, acc1.z); acc1.w = fmaf(p, v1.w, acc1.w);
    }
    float4 b0 = ((const float4*)bias)[lane * 2];
    float4 b1 = ((const float4*)bias)[lane * 2 + 1];
    float4 o0 = make_float4(fmaf(acc0.x, inv, b0.x), fmaf(acc0.y, inv, b0.y),
                            fmaf(acc0.z, inv, b0.z), fmaf(acc0.w, inv, b0.w));
    float4 o1 = make_float4(fmaf(acc1.x, inv, b1.x), fmaf(acc1.y, inv, b1.y),
                            fmaf(acc1.z, inv, b1.z), fmaf(acc1.w, inv, b1.w));
    float4* yr = (float4*)(y + (size_t)n * DH) + lane * 2;
    yr[0] = o0;
    yr[1] = o1;
}

__global__ void __launch_bounds__(256)
fused_agg10(const float* __restrict__ h3, const float* __restrict__ bias,
            float* __restrict__ out, int N) {
    int n = (blockIdx.x * blockDim.x + threadIdx.x) >> 5;
    int lane = threadIdx.x & 31;
    if (n >= N) return;
    int beg = g_row[n], end = g_row[n + 1];
    float ad = g_ad[n];

    float m = -INFINITY;
    for (int j = beg + lane; j < end; j += 32)
        m = fmaxf(m, leaky(g_as[g_col[j]] + ad));
#pragma unroll
    for (int o = 16; o > 0; o >>= 1)
        m = fmaxf(m, __shfl_xor_sync(0xFFFFFFFFu, m, o));

    float den = 0.0f;
    for (int j = beg + lane; j < end; j += 32)
        den += __expf(leaky(g_as[g_col[j]] + ad) - m);
#pragma unroll
    for (int o = 16; o > 0; o >>= 1)
        den += __shfl_xor_sync(0xFFFFFFFFu, den, o);
    float inv = 1.0f / den;

    float acc = 0.0f;
    for (int j = beg; j < end; j++) {
        int s = g_col[j];
        float p = __expf(leaky(g_as[s] + ad) - m);
        if (lane < COUT)
            acc = fmaf(p, h3[(size_t)s * COUT + lane], acc);
    }
    if (lane < COUT)
        out[(size_t)n * COUT + lane] = fmaf(acc, inv, bias[lane]);
}

// ---------------- layer 3 GEMM (D_out = 10), warp per node ----------------
__global__ void gemm_node3(const float* __restrict__ in, const float* __restrict__ W,
                           const float* __restrict__ a_s, const float* __restrict__ a_d,
                           float* __restrict__ h3, int N) {
    int n = (blockIdx.x * blockDim.x + threadIdx.x) >> 5;
    int lane = threadIdx.x & 31;
    if (n >= N) return;
    float acc[COUT];
#pragma unroll
    for (int c = 0; c < COUT; c++) acc[c] = 0.0f;
    const float* xr = in + (size_t)n * DH;
#pragma unroll
    for (int i = 0; i < DH / 32; i++) {
        int k = lane + i * 32;
        float v = fmaxf(xr[k], 0.0f);                 // relu on input
#pragma unroll
        for (int c = 0; c < COUT; c++)
            acc[c] = fmaf(v, W[k * COUT + c], acc[c]);
    }
#pragma unroll
    for (int c = 0; c < COUT; c++)
#pragma unroll
        for (int o = 16; o > 0; o >>= 1)
            acc[c] += __shfl_xor_sync(0xFFFFFFFFu, acc[c], o);
    if (lane == 0) {
        float ss = 0.0f, sd = 0.0f;
#pragma unroll
        for (int c = 0; c < COUT; c++) {
            h3[(size_t)n * COUT + c] = acc[c];
            ss = fmaf(acc[c], a_s[c], ss);
            sd = fmaf(acc[c], a_d[c], sd);
        }
        g_as[n] = ss;
        g_ad[n] = sd;
    }
}

// ---------------- host launcher ----------------
extern "C" void kernel_launch(void* const* d_in, const int* in_sizes, int n_in,
                              void* d_out, int out_size) {
    const float* x      = (const float*)d_in[0];
    const void*  ei     = d_in[1];
    const float* W1     = (const float*)d_in[2];
    const float* a_src1 = (const float*)d_in[3];
    const float* a_dst1 = (const float*)d_in[4];
    const float* b1     = (const float*)d_in[5];
    const float* W2     = (const float*)d_in[6];
    const float* a_src2 = (const float*)d_in[7];
    const float* a_dst2 = (const float*)d_in[8];
    const float* b2     = (const float*)d_in[9];
    const float* W3     = (const float*)d_in[10];
    const float* a_src3 = (const float*)d_in[11];
    const float* a_dst3 = (const float*)d_in[12];
    const float* b3     = (const float*)d_in[13];

    int N = in_sizes[0] / DH;      // 50000
    int E = in_sizes[1] / 2;       // 800000
    int ET = E + N;                // with self-loops

    float *h, *y, *h3;
    int* cnt;
    cudaGetSymbolAddress((void**)&h,   g_h);
    cudaGetSymbolAddress((void**)&y,   g_y);
    cudaGetSymbolAddress((void**)&h3,  g_h3);
    cudaGetSymbolAddress((void**)&cnt, g_cnt);
    float* out = (float*)d_out;

    detect_width_kernel<<<1, 256>>>((const int*)ei, E);

    // ---- CSR build (reused by all 3 layers) ----
    cudaMemsetAsync(cnt, 0, (size_t)N * sizeof(int));
    int edgeBlocks = (ET + 255) / 256;
    hist_kernel<<<edgeBlocks, 256>>>(ei, E, N);
    scan_kernel<<<1, 1024>>>(N);
    scatter_kernel<<<edgeBlocks, 256>>>(ei, E, N);

    dim3 ggrid(2, (N + 127) / 128);
    int nodeBlocks = (N * 32 + 255) / 256;

    // ---- layer 1 ----
    gemm_tc<false><<<ggrid, 256>>>(x, W1, h, N);
    node_alpha<<<nodeBlocks, 256>>>(h, a_src1, a_dst1, N);
    fused_agg256<<<nodeBlocks, 256>>>(h, b1, y, N);

    // ---- layer 2 ----
    gemm_tc<true><<<ggrid, 256>>>(y, W2, h, N);
    node_alpha<<<nodeBlocks, 256>>>(h, a_src2, a_dst2, N);
    fused_agg256<<<nodeBlocks, 256>>>(h, b2, y, N);

    // ---- layer 3 ----
    gemm_node3<<<nodeBlocks, 256>>>(y, W3, a_src3, a_dst3, h3, N);
    fused_agg10<<<nodeBlocks, 256>>>(h3, b3, out, N);
}

// round 7
// speedup vs baseline: 1.7306x; 1.0237x over previous
#include <cuda_runtime.h>
#include <cuda_bf16.h>
#include <cstdint>
#include <math.h>

// ---------------- problem constants ----------------
#define NMAX   50048          // nodes (50000, padded)
#define DH     256            // hidden dim
#define COUT   10             // output classes
#define EMAX   860064         // edges incl. self loops (800000 + 50000, padded)
#define NEG_SENTINEL -1e30f   // finite "-inf" so empty-lane online-softmax combines stay NaN-free

typedef unsigned int u32;

// ---------------- device scratch (no allocations allowed) ----------------
__device__ float g_h [ (size_t)NMAX * DH ];   // GEMM output / gather source
__device__ float g_y [ (size_t)NMAX * DH ];   // aggregation target / next input
__device__ float g_h3[ (size_t)NMAX * COUT ];
__device__ float g_as[NMAX];
__device__ float g_ad[NMAX];
__device__ int   g_cnt[NMAX];                 // histogram
__device__ int   g_row[NMAX + 1];             // CSR row offsets
__device__ int   g_cur[NMAX];                 // scatter cursors
__device__ int   g_col[EMAX];                 // CSR: src node per edge slot
__device__ int   g_is64;

// ---------------- helpers ----------------
__device__ __forceinline__ void get_edge(const void* ei, int E, int N, int i,
                                         int& s, int& d) {
    if (i < E) {
        if (g_is64) {
            const long long* p = (const long long*)ei;
            s = (int)p[i]; d = (int)p[E + i];
        } else {
            const int* p = (const int*)ei;
            s = p[i]; d = p[E + i];
        }
    } else {
        s = i - E; d = s;   // self loop
    }
}

// Detect whether edge_index is int64 or int32.
__global__ void detect_width_kernel(const int* ei2, int E) {
    __shared__ int any;
    if (threadIdx.x == 0) any = 0;
    __syncthreads();
    int limit = min(E, 2048);
    for (int j = threadIdx.x; j < limit; j += blockDim.x)
        if (ei2[2 * j + 1] != 0) any = 1;
    __syncthreads();
    if (threadIdx.x == 0) g_is64 = (any ? 0 : 1);
}

// ---------------- CSR build ----------------
__global__ void hist_kernel(const void* __restrict__ ei, int E, int N) {
    int i = blockIdx.x * blockDim.x + threadIdx.x;
    if (i >= E + N) return;
    int s, d;
    get_edge(ei, E, N, i, s, d);
    atomicAdd(&g_cnt[d], 1);
}

__global__ void scan_kernel(int N) {
    __shared__ int sh[1024];
    int t = threadIdx.x;
    int chunk = (N + 1023) >> 10;
    int b = t * chunk, e = min(b + chunk, N);
    int sum = 0;
    for (int i = b; i < e; i++) sum += g_cnt[i];
    sh[t] = sum;
    __syncthreads();
#pragma unroll
    for (int o = 1; o < 1024; o <<= 1) {
        int v = 0;
        if (t >= o) v = sh[t - o];
        __syncthreads();
        if (t >= o) sh[t] += v;
        __syncthreads();
    }
    int run = (t > 0) ? sh[t - 1] : 0;
    for (int i = b; i < e; i++) {
        g_row[i] = run;
        g_cur[i] = run;
        run += g_cnt[i];
    }
    if (t == 1023) g_row[N] = sh[1023];
}

__global__ void scatter_kernel(const void* __restrict__ ei, int E, int N) {
    int i = blockIdx.x * blockDim.x + threadIdx.x;
    if (i >= E + N) return;
    int s, d;
    get_edge(ei, E, N, i, s, d);
    int pos = atomicAdd(&g_cur[d], 1);
    g_col[pos] = s;
}

// ---------------- bf16 mma helper ----------------
__device__ __forceinline__ void mma16(float* c, const u32* a, const u32* b) {
    asm volatile(
        "mma.sync.aligned.m16n8k16.row.col.f32.bf16.bf16.f32 "
        "{%0,%1,%2,%3},{%4,%5,%6,%7},{%8,%9},{%0,%1,%2,%3};"
        : "+f"(c[0]), "+f"(c[1]), "+f"(c[2]), "+f"(c[3])
        : "r"(a[0]), "r"(a[1]), "r"(a[2]), "r"(a[3]),
          "r"(b[0]), "r"(b[1]));
}

// ---------------- tensor-core GEMM: C[M,256] = act(A[M,256]) @ B[256,256] --
// bf16 hi/lo fp32 emulation (3x bf16 m16n8k16).
// CTA tile 128x128, 8 warps, warp tile 32x64, K-chunk 32.
// Epilogue also accumulates alpha_src/alpha_dst partial dot products
// (g_as/g_ad must be zeroed before launch).
template<bool RELU>
__global__ void __launch_bounds__(256)
gemm_tc(const float* __restrict__ A, const float* __restrict__ B,
        float* __restrict__ C,
        const float* __restrict__ a_src, const float* __restrict__ a_dst,
        int M) {
    const int K = 256, N = 256;
    __shared__ __nv_bfloat162 Ash[128][17];   // 16 k-pairs + 1 pad
    __shared__ __nv_bfloat162 Asl[128][17];
    __shared__ __nv_bfloat162 Bsh[16][136];   // [kk][col]
    __shared__ __nv_bfloat162 Bsl[16][136];

    const int tid = threadIdx.x;
    const int bm = blockIdx.y, bn = blockIdx.x;
    const int wid = tid >> 5, lane = tid & 31;
    const int wm = wid >> 1;              // 0..3 : M offset wm*32
    const int wn = wid & 1;               // 0..1 : N offset wn*64
    const int g = lane >> 2, tig = lane & 3;

    float acc[2][8][4];
#pragma unroll
    for (int mt = 0; mt < 2; mt++)
#pragma unroll
        for (int nt = 0; nt < 8; nt++)
#pragma unroll
            for (int r = 0; r < 4; r++) acc[mt][nt][r] = 0.0f;

    for (int kc = 0; kc < K; kc += 32) {
        // ---- load A tile 128x32 fp32 -> bf16 hi/lo ----
#pragma unroll
        for (int i = 0; i < 4; i++) {
            int idx = tid + i * 256;        // 0..1023
            int row = idx >> 3;             // 0..127
            int c4  = idx & 7;              // 0..7
            int grow = bm * 128 + row;
            float4 v = make_float4(0, 0, 0, 0);
            if (grow < M)
                v = *(const float4*)(A + (size_t)grow * K + kc + c4 * 4);
            if (RELU) {
                v.x = fmaxf(v.x, 0.0f); v.y = fmaxf(v.y, 0.0f);
                v.z = fmaxf(v.z, 0.0f); v.w = fmaxf(v.w, 0.0f);
            }
            float e[4] = {v.x, v.y, v.z, v.w};
            __nv_bfloat16* ah = (__nv_bfloat16*)&Ash[row][0];
            __nv_bfloat16* al = (__nv_bfloat16*)&Asl[row][0];
#pragma unroll
            for (int j = 0; j < 4; j++) {
                int k = c4 * 4 + j;
                __nv_bfloat16 hb = __float2bfloat16(e[j]);
                float hf = __bfloat162float(hb);
                ah[k] = hb;
                al[k] = __float2bfloat16(e[j] - hf);
            }
        }
        // ---- load B tile 32x128 fp32 -> bf16 hi/lo, k-pair packed ----
#pragma unroll
        for (int i = 0; i < 4; i++) {
            int idx = tid + i * 256;
            int r  = idx >> 5;              // 0..31
            int c4 = idx & 31;              // 0..31
            float4 v = *(const float4*)(B + (size_t)(kc + r) * N + bn * 128 + c4 * 4);
            float e[4] = {v.x, v.y, v.z, v.w};
            int kk = r >> 1, par = r & 1;
#pragma unroll
            for (int j = 0; j < 4; j++) {
                int col = c4 * 4 + j;
                __nv_bfloat16 hb = __float2bfloat16(e[j]);
                float hf = __bfloat162float(hb);
                ((__nv_bfloat16*)&Bsh[kk][col])[par] = hb;
                ((__nv_bfloat16*)&Bsl[kk][col])[par] = __float2bfloat16(e[j] - hf);
            }
        }
        __syncthreads();

#pragma unroll
        for (int ks = 0; ks < 2; ks++) {
            int kb = ks * 8;
            u32 ah[2][4], al[2][4];
#pragma unroll
            for (int mt = 0; mt < 2; mt++) {
                int r0 = wm * 32 + mt * 16;
                ah[mt][0] = *(const u32*)&Ash[r0 + g][kb + tig];
                ah[mt][1] = *(const u32*)&Ash[r0 + g + 8][kb + tig];
                ah[mt][2] = *(const u32*)&Ash[r0 + g][kb + tig + 4];
                ah[mt][3] = *(const u32*)&Ash[r0 + g + 8][kb + tig + 4];
                al[mt][0] = *(const u32*)&Asl[r0 + g][kb + tig];
                al[mt][1] = *(const u32*)&Asl[r0 + g + 8][kb + tig];
                al[mt][2] = *(const u32*)&Asl[r0 + g][kb + tig + 4];
                al[mt][3] = *(const u32*)&Asl[r0 + g + 8][kb + tig + 4];
            }
            u32 bh[8][2], bl[8][2];
#pragma unroll
            for (int nt = 0; nt < 8; nt++) {
                int c0 = wn * 64 + nt * 8 + g;
                bh[nt][0] = *(const u32*)&Bsh[kb + tig][c0];
                bh[nt][1] = *(const u32*)&Bsh[kb + tig + 4][c0];
                bl[nt][0] = *(const u32*)&Bsl[kb + tig][c0];
                bl[nt][1] = *(const u32*)&Bsl[kb + tig + 4][c0];
            }
#pragma unroll
            for (int mt = 0; mt < 2; mt++)
#pragma unroll
                for (int nt = 0; nt < 8; nt++) {
                    mma16(acc[mt][nt], al[mt], bh[nt]);  // lo*hi
                    mma16(acc[mt][nt], ah[mt], bl[nt]);  // hi*lo
                    mma16(acc[mt][nt], ah[mt], bh[nt]);  // hi*hi
                }
        }
        __syncthreads();
    }

    // ---- store C + alpha partials ----
    float ss[2][2] = {{0, 0}, {0, 0}};   // [mt][row: g / g+8]
    float sd[2][2] = {{0, 0}, {0, 0}};
#pragma unroll
    for (int mt = 0; mt < 2; mt++) {
        int r0 = bm * 128 + wm * 32 + mt * 16 + g;
#pragma unroll
        for (int nt = 0; nt < 8; nt++) {
            int col = bn * 128 + wn * 64 + nt * 8 + 2 * tig;
            float a0 = a_src[col], a1 = a_src[col + 1];
            float d0 = a_dst[col], d1 = a_dst[col + 1];
            ss[mt][0] += acc[mt][nt][0] * a0 + acc[mt][nt][1] * a1;
            sd[mt][0] += acc[mt][nt][0] * d0 + acc[mt][nt][1] * d1;
            ss[mt][1] += acc[mt][nt][2] * a0 + acc[mt][nt][3] * a1;
            sd[mt][1] += acc[mt][nt][2] * d0 + acc[mt][nt][3] * d1;
            if (r0 < M)
                *(float2*)(C + (size_t)r0 * N + col) =
                    make_float2(acc[mt][nt][0], acc[mt][nt][1]);
            if (r0 + 8 < M)
                *(float2*)(C + (size_t)(r0 + 8) * N + col) =
                    make_float2(acc[mt][nt][2], acc[mt][nt][3]);
        }
    }
    // reduce across the quad (tig 0..3 share the same rows)
#pragma unroll
    for (int mt = 0; mt < 2; mt++)
#pragma unroll
        for (int r = 0; r < 2; r++) {
#pragma unroll
            for (int o = 1; o < 4; o <<= 1) {
                ss[mt][r] += __shfl_xor_sync(0xFFFFFFFFu, ss[mt][r], o);
                sd[mt][r] += __shfl_xor_sync(0xFFFFFFFFu, sd[mt][r], o);
            }
        }
    if (tig == 0) {
#pragma unroll
        for (int mt = 0; mt < 2; mt++) {
            int r0 = bm * 128 + wm * 32 + mt * 16 + g;
            if (r0 < M) {
                atomicAdd(&g_as[r0], ss[mt][0]);
                atomicAdd(&g_ad[r0], sd[mt][0]);
            }
            if (r0 + 8 < M) {
                atomicAdd(&g_as[r0 + 8], ss[mt][1]);
                atomicAdd(&g_ad[r0 + 8], sd[mt][1]);
            }
        }
    }
}

// ---------------- fused softmax + aggregation, warp per dst node ----------------
__device__ __forceinline__ float leaky(float v) {
    return v > 0.0f ? v : 0.2f * v;
}

// online (m, den) warp combine. m uses finite sentinel NEG_SENTINEL, so
// exp(m - mn) is always well-defined (exp(0)=1 against den=0 is identity).
__device__ __forceinline__ void warp_mden(float& m, float& den) {
#pragma unroll
    for (int o = 16; o > 0; o >>= 1) {
        float mo = __shfl_xor_sync(0xFFFFFFFFu, m, o);
        float do_ = __shfl_xor_sync(0xFFFFFFFFu, den, o);
        float mn = fmaxf(m, mo);
        den = den * __expf(m - mn) + do_ * __expf(mo - mn);
        m = mn;
    }
}

__global__ void __launch_bounds__(256)
fused_agg256(const float* __restrict__ h, const float* __restrict__ bias,
             float* __restrict__ y, int N) {
    int n = (blockIdx.x * blockDim.x + threadIdx.x) >> 5;
    int lane = threadIdx.x & 31;
    if (n >= N) return;
    int beg = g_row[n], end = g_row[n + 1];
    float ad = g_ad[n];

    // single online pass: max + denominator
    float m = NEG_SENTINEL, den = 0.0f;
    for (int j = beg + lane; j < end; j += 32) {
        float v = leaky(g_as[g_col[j]] + ad);
        float mn = fmaxf(m, v);
        den = den * __expf(m - mn) + __expf(v - mn);
        m = mn;
    }
    warp_mden(m, den);
    float inv = 1.0f / den;

    // accumulate (lane owns 8 contiguous floats of the 256-dim row)
    float4 acc0 = make_float4(0, 0, 0, 0);
    float4 acc1 = make_float4(0, 0, 0, 0);
    for (int j = beg; j < end; j++) {
        int s = g_col[j];                       // broadcast
        float p = __expf(leaky(g_as[s] + ad) - m);
        const float4* hr = (const float4*)(h + (size_t)s * DH) + lane * 2;
        float4 v0 = hr[0], v1 = hr[1];
        acc0.x = fmaf(p, v0.x, acc0.x); acc0.y = fmaf(p, v0.y, acc0.y);
        acc0.z = fmaf(p, v0.z, acc0.z); acc0.w = fmaf(p, v0.w, acc0.w);
        acc1.x = fmaf(p, v1.x, acc1.x); acc1.y = fmaf(p, v1.y, acc1.y);
        acc1.z = fmaf(p, v1.z, acc1.z); acc1.w = fmaf(p, v1.w, acc1.w);
    }
    float4 b0 = ((const float4*)bias)[lane * 2];
    float4 b1 = ((const float4*)bias)[lane * 2 + 1];
    float4 o0 = make_float4(fmaf(acc0.x, inv, b0.x), fmaf(acc0.y, inv, b0.y),
                            fmaf(acc0.z, inv, b0.z), fmaf(acc0.w, inv, b0.w));
    float4 o1 = make_float4(fmaf(acc1.x, inv, b1.x), fmaf(acc1.y, inv, b1.y),
                            fmaf(acc1.z, inv, b1.z), fmaf(acc1.w, inv, b1.w));
    float4* yr = (float4*)(y + (size_t)n * DH) + lane * 2;
    yr[0] = o0;
    yr[1] = o1;
}

__global__ void __launch_bounds__(256)
fused_agg10(const float* __restrict__ h3, const float* __restrict__ bias,
            float* __restrict__ out, int N) {
    int n = (blockIdx.x * blockDim.x + threadIdx.x) >> 5;
    int lane = threadIdx.x & 31;
    if (n >= N) return;
    int beg = g_row[n], end = g_row[n + 1];
    float ad = g_ad[n];

    float m = NEG_SENTINEL, den = 0.0f;
    for (int j = beg + lane; j < end; j += 32) {
        float v = leaky(g_as[g_col[j]] + ad);
        float mn = fmaxf(m, v);
        den = den * __expf(m - mn) + __expf(v - mn);
        m = mn;
    }
    warp_mden(m, den);
    float inv = 1.0f / den;

    float acc = 0.0f;
    for (int j = beg; j < end; j++) {
        int s = g_col[j];
        float p = __expf(leaky(g_as[s] + ad) - m);
        if (lane < COUT)
            acc = fmaf(p, h3[(size_t)s * COUT + lane], acc);
    }
    if (lane < COUT)
        out[(size_t)n * COUT + lane] = fmaf(acc, inv, bias[lane]);
}

// ---------------- layer 3 GEMM (D_out = 10), warp per node ----------------
__global__ void gemm_node3(const float* __restrict__ in, const float* __restrict__ W,
                           const float* __restrict__ a_s, const float* __restrict__ a_d,
                           float* __restrict__ h3, int N) {
    int n = (blockIdx.x * blockDim.x + threadIdx.x) >> 5;
    int lane = threadIdx.x & 31;
    if (n >= N) return;
    float acc[COUT];
#pragma unroll
    for (int c = 0; c < COUT; c++) acc[c] = 0.0f;
    const float* xr = in + (size_t)n * DH;
#pragma unroll
    for (int i = 0; i < DH / 32; i++) {
        int k = lane + i * 32;
        float v = fmaxf(xr[k], 0.0f);                 // relu on input
#pragma unroll
        for (int c = 0; c < COUT; c++)
            acc[c] = fmaf(v, W[k * COUT + c], acc[c]);
    }
#pragma unroll
    for (int c = 0; c < COUT; c++)
#pragma unroll
        for (int o = 16; o > 0; o >>= 1)
            acc[c] += __shfl_xor_sync(0xFFFFFFFFu, acc[c], o);
    if (lane == 0) {
        float ss = 0.0f, sd = 0.0f;
#pragma unroll
        for (int c = 0; c < COUT; c++) {
            h3[(size_t)n * COUT + c] = acc[c];
            ss = fmaf(acc[c], a_s[c], ss);
            sd = fmaf(acc[c], a_d[c], sd);
        }
        g_as[n] = ss;
        g_ad[n] = sd;
    }
}

// ---------------- host launcher ----------------
extern "C" void kernel_launch(void* const* d_in, const int* in_sizes, int n_in,
                              void* d_out, int out_size) {
    const float* x      = (const float*)d_in[0];
    const void*  ei     = d_in[1];
    const float* W1     = (const float*)d_in[2];
    const float* a_src1 = (const float*)d_in[3];
    const float* a_dst1 = (const float*)d_in[4];
    const float* b1     = (const float*)d_in[5];
    const float* W2     = (const float*)d_in[6];
    const float* a_src2 = (const float*)d_in[7];
    const float* a_dst2 = (const float*)d_in[8];
    const float* b2     = (const float*)d_in[9];
    const float* W3     = (const float*)d_in[10];
    const float* a_src3 = (const float*)d_in[11];
    const float* a_dst3 = (const float*)d_in[12];
    const float* b3     = (const float*)d_in[13];

    int N = in_sizes[0] / DH;      // 50000
    int E = in_sizes[1] / 2;       // 800000
    int ET = E + N;                // with self-loops

    float *h, *y, *h3, *as, *adp;
    int* cnt;
    cudaGetSymbolAddress((void**)&h,   g_h);
    cudaGetSymbolAddress((void**)&y,   g_y);
    cudaGetSymbolAddress((void**)&h3,  g_h3);
    cudaGetSymbolAddress((void**)&as,  g_as);
    cudaGetSymbolAddress((void**)&adp, g_ad);
    cudaGetSymbolAddress((void**)&cnt, g_cnt);
    float* out = (float*)d_out;

    detect_width_kernel<<<1, 256>>>((const int*)ei, E);

    // ---- CSR build (reused by all 3 layers) ----
    cudaMemsetAsync(cnt, 0, (size_t)N * sizeof(int));
    int edgeBlocks = (ET + 255) / 256;
    hist_kernel<<<edgeBlocks, 256>>>(ei, E, N);
    scan_kernel<<<1, 1024>>>(N);
    scatter_kernel<<<edgeBlocks, 256>>>(ei, E, N);

    dim3 ggrid(2, (N + 127) / 128);
    int nodeBlocks = (N * 32 + 255) / 256;

    // ---- layer 1 ----
    cudaMemsetAsync(as,  0, (size_t)N * sizeof(float));
    cudaMemsetAsync(adp, 0, (size_t)N * sizeof(float));
    gemm_tc<false><<<ggrid, 256>>>(x, W1, h, a_src1, a_dst1, N);
    fused_agg256<<<nodeBlocks, 256>>>(h, b1, y, N);

    // ---- layer 2 ----
    cudaMemsetAsync(as,  0, (size_t)N * sizeof(float));
    cudaMemsetAsync(adp, 0, (size_t)N * sizeof(float));
    gemm_tc<true><<<ggrid, 256>>>(y, W2, h, a_src2, a_dst2, N);
    fused_agg256<<<nodeBlocks, 256>>>(h, b2, y, N);

    // ---- layer 3 ----
    gemm_node3<<<nodeBlocks, 256>>>(y, W3, a_src3, a_dst3, h3, N);
    fused_agg10<<<nodeBlocks, 256>>>(h3, b3, out, N);
}